// round 9
// baseline (speedup 1.0000x reference)
#include <cuda_runtime.h>

// KAN layer as a fused dense GEMM, 2 launches.
//   kan_c2t   : C2t[k][o] = mask*scale_sp*coef (j<8) | mask*scale_base (j=8),
//               k = i*9+j, K = 576. 147 KB -> L2/L1-resident.
//   kan_fused : per block (16 batch rows x all 64 o):
//               (a) compute dense feature tile Fs[576][16] in smem
//                   (4 nonzero cubic-B-spline weights scattered + silu),
//               (b) full-K GEMM: thread tile 2o x 4b via packed fp32
//                   fma.rn.f32x2; A = smem broadcast LDS.128, B = LDG.64
//                   from L1-resident C2t; no barriers in the hot loop,
//               (c) direct output store (no split-K, no reduce kernel).

#define IN_DIM  64
#define OUT_DIM 64
#define KDIM    (IN_DIM * 9)   // 576
#define MTILE   16
#define THREADS 128

__device__ __align__(16) float g_C2t[KDIM * OUT_DIM];   // [k][o], 144 KB

typedef unsigned long long ull;

__device__ __forceinline__ void ffma2(ull& d, ull a, ull b) {
    asm("fma.rn.f32x2 %0, %1, %2, %0;" : "+l"(d) : "l"(a), "l"(b));
}
__device__ __forceinline__ ull dup2(float v) {
    ull r;
    asm("mov.b64 %0, {%1, %1};" : "=l"(r) : "f"(v));
    return r;
}
__device__ __forceinline__ float2 unpack2(ull v) {
    float2 r;
    asm("mov.b64 {%0, %1}, %2;" : "=f"(r.x), "=f"(r.y) : "l"(v));
    return r;
}

// ---------------- coefficient matrix --------------------------------------
__global__ __launch_bounds__(256)
void kan_c2t(const float* __restrict__ coefp,
             const float* __restrict__ sbase,
             const float* __restrict__ ssp,
             const float* __restrict__ maskp)
{
    const int tid = blockIdx.x * blockDim.x + threadIdx.x;  // = k*64 + o
    if (tid >= KDIM * OUT_DIM) return;
    const int o = tid & (OUT_DIM - 1);
    const int k = tid >> 6;
    const int i = k / 9;
    const int j = k - i * 9;
    const int s = o * IN_DIM + i;
    const float m = maskp[s];
    g_C2t[tid] = (j < 8) ? m * ssp[s] * __ldg(coefp + s * 8 + j)
                         : m * sbase[s];
}

// ---------------- fused features + GEMM -----------------------------------
__global__ __launch_bounds__(THREADS, 1)
void kan_fused(const float* __restrict__ inp,
               const float* __restrict__ gridp,
               float* __restrict__ out,
               int batch)
{
    __shared__ __align__(16) float Fs[KDIM][MTILE];   // 36.9 KB

    const int tid = threadIdx.x;
    const int b0  = blockIdx.x * MTILE;

    // ---- feature tile: thread owns input i = tid/2, 8 consecutive b's ----
    {
        const int i  = tid >> 1;
        const int bq = (tid & 1) * 8;
        const float g0   = __ldg(gridp + i * 6 + 0);
        const float g5   = __ldg(gridp + i * 6 + 5);
        const float h    = (g5 - g0) * 0.2f;
        const float t0   = g0 - 3.0f * h;
        const float invh = 1.0f / h;

        #pragma unroll
        for (int q = 0; q < 8; ++q) {
            const int bl = bq + q;
            const int b  = b0 + bl;
            const float x = (b < batch) ? inp[b * IN_DIM + i] : 0.0f;

            const float mf = (x - t0) * invh;
            int mi = (int)floorf(mf);
            const float okf = (mi >= 0 && mi < 11) ? 1.0f : 0.0f;
            mi = max(0, min(10, mi));

            const float u  = mf - (float)mi;
            const float v  = 1.0f - u;
            const float u2 = u * u;
            const float u3 = u2 * u;
            float w[4];
            w[0] = okf * (v * v * v * (1.0f / 6.0f));
            w[3] = okf * (u3 * (1.0f / 6.0f));
            w[1] = okf * ((2.0f / 3.0f) - u2 + 0.5f * u3);
            w[2] = okf - w[0] - w[1] - w[3];

            float f[9];
            #pragma unroll
            for (int j = 0; j < 9; ++j) f[j] = 0.0f;
            #pragma unroll
            for (int r = 0; r < 4; ++r) {
                const int j = mi - 3 + r;
                if (j >= 0 && j < 8) f[j] = w[r];
            }
            f[8] = __fdividef(x, 1.0f + __expf(-x));   // silu

            #pragma unroll
            for (int j = 0; j < 9; ++j)
                Fs[i * 9 + j][bl] = f[j];
        }
    }
    __syncthreads();

    // ---- GEMM: warp w -> o in [w*16, w*16+16); lane: ox(0..7) x by(0..3)
    const int w    = tid >> 5;
    const int lane = tid & 31;
    const int ox   = lane >> 2;
    const int by   = lane & 3;
    const int o0   = w * 16 + ox * 2;

    ull acc00 = 0, acc01 = 0, acc10 = 0, acc11 = 0;  // [o][bpair]

    const float* bbase = g_C2t + o0;

    #pragma unroll 8
    for (int k = 0; k < KDIM; ++k) {
        const ulonglong2 a = *(const ulonglong2*)(&Fs[k][by * 4]);
        const float2 bv = __ldg((const float2*)(bbase + k * OUT_DIM));
        const ull bx = dup2(bv.x);
        const ull byv = dup2(bv.y);
        ffma2(acc00, a.x, bx);
        ffma2(acc01, a.y, bx);
        ffma2(acc10, a.x, byv);
        ffma2(acc11, a.y, byv);
    }

    // ---- store: thread has (o0, o0+1) x (b0+by*4 .. +3) ----
    const float2 r00 = unpack2(acc00);   // o0:   b+0, b+1
    const float2 r01 = unpack2(acc01);   // o0:   b+2, b+3
    const float2 r10 = unpack2(acc10);   // o0+1: b+0, b+1
    const float2 r11 = unpack2(acc11);   // o0+1: b+2, b+3

    const float ro0[4] = { r00.x, r00.y, r01.x, r01.y };
    const float ro1[4] = { r10.x, r10.y, r11.x, r11.y };

    #pragma unroll
    for (int bb = 0; bb < 4; ++bb) {
        const int b = b0 + by * 4 + bb;
        if (b < batch)
            *(float2*)&out[b * OUT_DIM + o0] = make_float2(ro0[bb], ro1[bb]);
    }
}

extern "C" void kernel_launch(void* const* d_in, const int* in_sizes, int n_in,
                              void* d_out, int out_size)
{
    const float* inp   = (const float*)d_in[0];   // (batch, 64)
    const float* gridp = (const float*)d_in[1];   // (4096, 6)
    const float* coefp = (const float*)d_in[2];   // (4096, 8)
    const float* sbase = (const float*)d_in[3];   // (4096,)
    const float* ssp   = (const float*)d_in[4];   // (4096,)
    const float* maskp = (const float*)d_in[5];   // (4096,)
    float* out = (float*)d_out;                   // (batch, 64)

    const int batch = in_sizes[0] / IN_DIM;

    kan_c2t<<<(KDIM * OUT_DIM + 255) / 256, 256>>>(coefp, sbase, ssp, maskp);

    const int blocks = (batch + MTILE - 1) / MTILE;   // 128 @ batch=2048
    kan_fused<<<blocks, THREADS>>>(inp, gridp, out, batch);
}

// round 10
// speedup vs baseline: 1.0702x; 1.0702x over previous
#include <cuda_runtime.h>

// KAN layer as fused dense GEMM, 2 launches.
//   kan_c2t   : C2t[k][o] = mask*scale_sp*coef (j<8) | mask*scale_base (j=8),
//               k = i*9+j, K=576, 144 KB -> L1/L2-resident.
//   kan_fused : block = 4 batch rows x all 64 o, 256 threads, 512 blocks.
//               (a) feature tile Fs[576][4] in smem (4 nonzero cubic
//                   B-spline weights scattered densely + silu),
//               (b) warp-level split-K: each of 8 warps owns 72 k's and a
//                   full 4b x 64o partial tile (4 packed f32x2 accs/lane;
//                   per k: 1 broadcast LDS + 2 LDG.128 + 4 FFMA2),
//               (c) fixed-order in-block reduce over the 8 warp partials
//                   (deterministic), coalesced store.

#define IN_DIM  64
#define OUT_DIM 64
#define KDIM    (IN_DIM * 9)   // 576
#define MTILE   4
#define THREADS 256
#define NWARP   8
#define KSLICE  (KDIM / NWARP) // 72

__device__ __align__(16) float g_C2t[KDIM * OUT_DIM];   // [k][o], 144 KB

typedef unsigned long long ull;

__device__ __forceinline__ void ffma2(ull& d, ull a, ull b) {
    asm("fma.rn.f32x2 %0, %1, %2, %0;" : "+l"(d) : "l"(a), "l"(b));
}
__device__ __forceinline__ ull dup2(float v) {
    ull r;
    asm("mov.b64 %0, {%1, %1};" : "=l"(r) : "f"(v));
    return r;
}

// ---------------- coefficient matrix --------------------------------------
__global__ __launch_bounds__(256)
void kan_c2t(const float* __restrict__ coefp,
             const float* __restrict__ sbase,
             const float* __restrict__ ssp,
             const float* __restrict__ maskp)
{
    const int tid = blockIdx.x * blockDim.x + threadIdx.x;  // = k*64 + o
    if (tid >= KDIM * OUT_DIM) return;
    const int o = tid & (OUT_DIM - 1);
    const int k = tid >> 6;
    const int i = k / 9;
    const int j = k - i * 9;
    const int s = o * IN_DIM + i;
    const float m = maskp[s];
    g_C2t[tid] = (j < 8) ? m * ssp[s] * __ldg(coefp + s * 8 + j)
                         : m * sbase[s];
}

// ---------------- fused features + GEMM -----------------------------------
__global__ __launch_bounds__(THREADS)
void kan_fused(const float* __restrict__ inp,
               const float* __restrict__ gridp,
               float* __restrict__ out,
               int batch)
{
    __shared__ __align__(16) float Fs[KDIM * MTILE];            // 9.2 KB
    __shared__ __align__(16) float Ps[NWARP * MTILE * OUT_DIM]; // 8.0 KB

    const int tid = threadIdx.x;
    const int b0  = blockIdx.x * MTILE;

    // ---- features: thread owns (i = tid/4, bl = tid%4) ----
    {
        const int i  = tid >> 2;
        const int bl = tid & 3;
        const int b  = b0 + bl;
        const float x = (b < batch) ? inp[b * IN_DIM + i] : 0.0f;

        const float g0 = __ldg(gridp + i * 6 + 0);
        const float g5 = __ldg(gridp + i * 6 + 5);
        const float h  = (g5 - g0) * 0.2f;
        const float mf = (x - (g0 - 3.0f * h)) * (1.0f / h);

        int mi = (int)floorf(mf);
        const float okf = (mi >= 0 && mi < 11) ? 1.0f : 0.0f;
        mi = max(0, min(10, mi));

        const float u  = mf - (float)mi;
        const float v  = 1.0f - u;
        const float u2 = u * u;
        const float u3 = u2 * u;
        float wgt[4];
        wgt[0] = okf * (v * v * v * (1.0f / 6.0f));
        wgt[3] = okf * (u3 * (1.0f / 6.0f));
        wgt[1] = okf * ((2.0f / 3.0f) - u2 + 0.5f * u3);
        wgt[2] = okf - wgt[0] - wgt[1] - wgt[3];

        float f[9];
        #pragma unroll
        for (int j = 0; j < 9; ++j) f[j] = 0.0f;
        #pragma unroll
        for (int r = 0; r < 4; ++r) {
            const int j = mi - 3 + r;
            if (j >= 0 && j < 8) f[j] = wgt[r];
        }
        f[8] = __fdividef(x, 1.0f + __expf(-x));   // silu

        #pragma unroll
        for (int j = 0; j < 9; ++j)
            Fs[(i * 9 + j) * MTILE + bl] = f[j];
    }
    __syncthreads();

    // ---- warp split-K GEMM ----
    const int w    = tid >> 5;       // warp -> k slice
    const int lane = tid & 31;
    const int bq   = lane & 3;       // batch row within tile
    const int og   = lane >> 2;      // o-group of 8 (0..7)

    ull acc0 = 0, acc1 = 0, acc2 = 0, acc3 = 0;   // o-pairs og*8 + {01,23,45,67}

    const float* crow = g_C2t + og * 8;
    const int kbeg = w * KSLICE;

    #pragma unroll 4
    for (int k = kbeg; k < kbeg + KSLICE; ++k) {
        const ull a2 = dup2(Fs[k * MTILE + bq]);           // broadcast LDS
        union { float4 f; ulonglong2 u; } cA, cB;          // packed-pair bitcast
        cA.f = __ldg((const float4*)(crow + k * OUT_DIM));
        cB.f = __ldg((const float4*)(crow + k * OUT_DIM + 4));
        ffma2(acc0, a2, cA.u.x);
        ffma2(acc1, a2, cA.u.y);
        ffma2(acc2, a2, cB.u.x);
        ffma2(acc3, a2, cB.u.y);
    }

    // partial tile -> smem: Ps[w][bq][o]
    {
        ulonglong2* pdst =
            (ulonglong2*)(Ps + (w * MTILE + bq) * OUT_DIM + og * 8);
        ulonglong2 v0; v0.x = acc0; v0.y = acc1;
        ulonglong2 v1; v1.x = acc2; v1.y = acc3;
        pdst[0] = v0;
        pdst[1] = v1;
    }
    __syncthreads();

    // ---- fixed-order reduce over 8 warp partials, coalesced store ----
    {
        const int bl = tid >> 6;          // 0..3
        const int o  = tid & 63;
        float v = 0.0f;
        #pragma unroll
        for (int ww = 0; ww < NWARP; ++ww)
            v += Ps[(ww * MTILE + bl) * OUT_DIM + o];
        const int b = b0 + bl;
        if (b < batch)
            out[b * OUT_DIM + o] = v;
    }
}

extern "C" void kernel_launch(void* const* d_in, const int* in_sizes, int n_in,
                              void* d_out, int out_size)
{
    const float* inp   = (const float*)d_in[0];   // (batch, 64)
    const float* gridp = (const float*)d_in[1];   // (4096, 6)
    const float* coefp = (const float*)d_in[2];   // (4096, 8)
    const float* sbase = (const float*)d_in[3];   // (4096,)
    const float* ssp   = (const float*)d_in[4];   // (4096,)
    const float* maskp = (const float*)d_in[5];   // (4096,)
    float* out = (float*)d_out;                   // (batch, 64)

    const int batch = in_sizes[0] / IN_DIM;

    kan_c2t<<<(KDIM * OUT_DIM + 255) / 256, 256>>>(coefp, sbase, ssp, maskp);

    const int blocks = (batch + MTILE - 1) / MTILE;   // 512 @ batch=2048
    kan_fused<<<blocks, THREADS>>>(inp, gridp, out, batch);
}

// round 11
// speedup vs baseline: 1.1509x; 1.0754x over previous
#include <cuda_runtime.h>

// KAN layer as fused dense GEMM, 2 launches.
//   kan_c2t   : C2t[k][o] = mask*scale_sp*coef (j<8) | mask*scale_base (j=8),
//               k = i*9+j, K=576, 144 KB -> L1/L2-resident.
//   kan_fused : block = 4 batch rows x all 64 o, 256 threads, 512 blocks.
//               (a) feature tile Fs[576][4] in smem,
//               (b) warp-level split-K (72 k's per warp), inner loop in
//                   groups of 4 k's with ALL loads issued before the FMAs
//                   (8 LDG.128 + 4 LDS in flight, x2 via unroll), packed
//                   f32x2 FMAs; __launch_bounds__(256,3) to un-starve regs,
//               (c) fixed-order in-block reduce (deterministic), coalesced
//                   store.

#define IN_DIM  64
#define OUT_DIM 64
#define KDIM    (IN_DIM * 9)   // 576
#define MTILE   4
#define THREADS 256
#define NWARP   8
#define KSLICE  (KDIM / NWARP) // 72
#define KG      4              // k's per load/compute group

__device__ __align__(16) float g_C2t[KDIM * OUT_DIM];   // [k][o], 144 KB

typedef unsigned long long ull;

__device__ __forceinline__ void ffma2(ull& d, ull a, ull b) {
    asm("fma.rn.f32x2 %0, %1, %2, %0;" : "+l"(d) : "l"(a), "l"(b));
}
__device__ __forceinline__ ull dup2(float v) {
    ull r;
    asm("mov.b64 %0, {%1, %1};" : "=l"(r) : "f"(v));
    return r;
}

// ---------------- coefficient matrix --------------------------------------
__global__ __launch_bounds__(256)
void kan_c2t(const float* __restrict__ coefp,
             const float* __restrict__ sbase,
             const float* __restrict__ ssp,
             const float* __restrict__ maskp)
{
    const int tid = blockIdx.x * blockDim.x + threadIdx.x;  // = k*64 + o
    if (tid >= KDIM * OUT_DIM) return;
    const int o = tid & (OUT_DIM - 1);
    const int k = tid >> 6;
    const int i = k / 9;
    const int j = k - i * 9;
    const int s = o * IN_DIM + i;
    const float m = maskp[s];
    g_C2t[tid] = (j < 8) ? m * ssp[s] * __ldg(coefp + s * 8 + j)
                         : m * sbase[s];
}

// ---------------- fused features + GEMM -----------------------------------
__global__ __launch_bounds__(THREADS, 3)
void kan_fused(const float* __restrict__ inp,
               const float* __restrict__ gridp,
               float* __restrict__ out,
               int batch)
{
    __shared__ __align__(16) float Fs[KDIM * MTILE];            // 9.2 KB
    __shared__ __align__(16) float Ps[NWARP * MTILE * OUT_DIM]; // 8.0 KB

    const int tid = threadIdx.x;
    const int b0  = blockIdx.x * MTILE;

    // ---- features: thread owns (i = tid/4, bl = tid%4) ----
    {
        const int i  = tid >> 2;
        const int bl = tid & 3;
        const int b  = b0 + bl;
        const float x = (b < batch) ? inp[b * IN_DIM + i] : 0.0f;

        const float g0 = __ldg(gridp + i * 6 + 0);
        const float g5 = __ldg(gridp + i * 6 + 5);
        const float h  = (g5 - g0) * 0.2f;
        const float mf = (x - (g0 - 3.0f * h)) * (1.0f / h);

        int mi = (int)floorf(mf);
        const float okf = (mi >= 0 && mi < 11) ? 1.0f : 0.0f;
        mi = max(0, min(10, mi));

        const float u  = mf - (float)mi;
        const float v  = 1.0f - u;
        const float u2 = u * u;
        const float u3 = u2 * u;
        float wgt[4];
        wgt[0] = okf * (v * v * v * (1.0f / 6.0f));
        wgt[3] = okf * (u3 * (1.0f / 6.0f));
        wgt[1] = okf * ((2.0f / 3.0f) - u2 + 0.5f * u3);
        wgt[2] = okf - wgt[0] - wgt[1] - wgt[3];

        float f[9];
        #pragma unroll
        for (int j = 0; j < 9; ++j) f[j] = 0.0f;
        #pragma unroll
        for (int r = 0; r < 4; ++r) {
            const int j = mi - 3 + r;
            if (j >= 0 && j < 8) f[j] = wgt[r];
        }
        f[8] = __fdividef(x, 1.0f + __expf(-x));   // silu

        #pragma unroll
        for (int j = 0; j < 9; ++j)
            Fs[(i * 9 + j) * MTILE + bl] = f[j];
    }
    __syncthreads();

    // ---- warp split-K GEMM ----
    const int w    = tid >> 5;       // warp -> k slice
    const int lane = tid & 31;
    const int bq   = lane & 3;       // batch row within tile
    const int og   = lane >> 2;      // o-group of 8 (0..7)

    ull acc0 = 0, acc1 = 0, acc2 = 0, acc3 = 0;   // o-pairs og*8 + {01,23,45,67}

    const float* crow = g_C2t + og * 8;
    const int kbeg = w * KSLICE;

    #pragma unroll 2
    for (int g = 0; g < KSLICE / KG; ++g) {
        const int kb = kbeg + g * KG;

        // phase 1: issue ALL loads for the group (independent -> MLP)
        float a[KG];
        float4 cA[KG], cB[KG];
        #pragma unroll
        for (int j = 0; j < KG; ++j) {
            const int k = kb + j;
            a[j]  = Fs[k * MTILE + bq];                       // LDS broadcast
            cA[j] = __ldg((const float4*)(crow + k * OUT_DIM));
            cB[j] = __ldg((const float4*)(crow + k * OUT_DIM + 4));
        }

        // phase 2: consume with packed FMAs
        #pragma unroll
        for (int j = 0; j < KG; ++j) {
            const ull a2 = dup2(a[j]);
            union { float4 f; ulonglong2 u; } uA, uB;
            uA.f = cA[j];
            uB.f = cB[j];
            ffma2(acc0, a2, uA.u.x);
            ffma2(acc1, a2, uA.u.y);
            ffma2(acc2, a2, uB.u.x);
            ffma2(acc3, a2, uB.u.y);
        }
    }

    // partial tile -> smem: Ps[w][bq][o]
    {
        ulonglong2* pdst =
            (ulonglong2*)(Ps + (w * MTILE + bq) * OUT_DIM + og * 8);
        ulonglong2 v0; v0.x = acc0; v0.y = acc1;
        ulonglong2 v1; v1.x = acc2; v1.y = acc3;
        pdst[0] = v0;
        pdst[1] = v1;
    }
    __syncthreads();

    // ---- fixed-order reduce over 8 warp partials, coalesced store ----
    {
        const int bl = tid >> 6;          // 0..3
        const int o  = tid & 63;
        float v = 0.0f;
        #pragma unroll
        for (int ww = 0; ww < NWARP; ++ww)
            v += Ps[(ww * MTILE + bl) * OUT_DIM + o];
        const int b = b0 + bl;
        if (b < batch)
            out[b * OUT_DIM + o] = v;
    }
}

extern "C" void kernel_launch(void* const* d_in, const int* in_sizes, int n_in,
                              void* d_out, int out_size)
{
    const float* inp   = (const float*)d_in[0];   // (batch, 64)
    const float* gridp = (const float*)d_in[1];   // (4096, 6)
    const float* coefp = (const float*)d_in[2];   // (4096, 8)
    const float* sbase = (const float*)d_in[3];   // (4096,)
    const float* ssp   = (const float*)d_in[4];   // (4096,)
    const float* maskp = (const float*)d_in[5];   // (4096,)
    float* out = (float*)d_out;                   // (batch, 64)

    const int batch = in_sizes[0] / IN_DIM;

    kan_c2t<<<(KDIM * OUT_DIM + 255) / 256, 256>>>(coefp, sbase, ssp, maskp);

    const int blocks = (batch + MTILE - 1) / MTILE;   // 512 @ batch=2048
    kan_fused<<<blocks, THREADS>>>(inp, gridp, out, batch);
}

// round 12
// speedup vs baseline: 1.4922x; 1.2966x over previous
#include <cuda_runtime.h>

// KAN layer as fused dense GEMM, 2 launches.
//   kan_c2t   : C2t[k][o] = mask*scale_sp*coef (j<8) | mask*scale_base (j=8),
//               k = i*9+j, K=576, 144 KB -> L1/L2-resident.
//   kan_fused : block = 4 batch rows x all 64 o, 128 threads (4 warps),
//               512 blocks -> ~14 warps/SM, ALL resident in ONE wave (no
//               tail wave). Warp-level split-K (144 k per warp), inner loop
//               double-buffered: group g+1's 8 LDG.128 + 4 LDS are issued
//               before group g's packed-f32x2 FMAs consume, so L1-hit
//               latency is pipelined. Fixed-order in-block reduce
//               (deterministic), coalesced store.

#define IN_DIM  64
#define OUT_DIM 64
#define KDIM    (IN_DIM * 9)   // 576
#define MTILE   4
#define THREADS 128
#define NWARP   4
#define KSLICE  (KDIM / NWARP) // 144
#define KG      4              // k's per pipeline stage
#define NGRP    (KSLICE / KG)  // 36

__device__ __align__(16) float g_C2t[KDIM * OUT_DIM];   // [k][o], 144 KB

typedef unsigned long long ull;

__device__ __forceinline__ void ffma2(ull& d, ull a, ull b) {
    asm("fma.rn.f32x2 %0, %1, %2, %0;" : "+l"(d) : "l"(a), "l"(b));
}
__device__ __forceinline__ ull dup2(float v) {
    ull r;
    asm("mov.b64 %0, {%1, %1};" : "=l"(r) : "f"(v));
    return r;
}

// ---------------- coefficient matrix --------------------------------------
__global__ __launch_bounds__(256)
void kan_c2t(const float* __restrict__ coefp,
             const float* __restrict__ sbase,
             const float* __restrict__ ssp,
             const float* __restrict__ maskp)
{
    const int tid = blockIdx.x * blockDim.x + threadIdx.x;  // = k*64 + o
    if (tid >= KDIM * OUT_DIM) return;
    const int o = tid & (OUT_DIM - 1);
    const int k = tid >> 6;
    const int i = k / 9;
    const int j = k - i * 9;
    const int s = o * IN_DIM + i;
    const float m = maskp[s];
    g_C2t[tid] = (j < 8) ? m * ssp[s] * __ldg(coefp + s * 8 + j)
                         : m * sbase[s];
}

// ---------------- fused features + GEMM -----------------------------------
__global__ __launch_bounds__(THREADS)
void kan_fused(const float* __restrict__ inp,
               const float* __restrict__ gridp,
               float* __restrict__ out,
               int batch)
{
    __shared__ __align__(16) float Fs[KDIM * MTILE];            // 9.2 KB
    __shared__ __align__(16) float Ps[NWARP * MTILE * OUT_DIM]; // 4.0 KB

    const int tid = threadIdx.x;
    const int b0  = blockIdx.x * MTILE;

    // ---- features: 256 items (64 i x 4 bl), 2 per thread ----
    #pragma unroll
    for (int rep = 0; rep < 2; ++rep) {
        const int item = tid + rep * THREADS;
        const int i  = item >> 2;
        const int bl = item & 3;
        const int b  = b0 + bl;
        const float x = (b < batch) ? inp[b * IN_DIM + i] : 0.0f;

        const float g0 = __ldg(gridp + i * 6 + 0);
        const float g5 = __ldg(gridp + i * 6 + 5);
        const float h  = (g5 - g0) * 0.2f;
        const float mf = (x - (g0 - 3.0f * h)) * (1.0f / h);

        int mi = (int)floorf(mf);
        const float okf = (mi >= 0 && mi < 11) ? 1.0f : 0.0f;
        mi = max(0, min(10, mi));

        const float u  = mf - (float)mi;
        const float v  = 1.0f - u;
        const float u2 = u * u;
        const float u3 = u2 * u;
        float wgt[4];
        wgt[0] = okf * (v * v * v * (1.0f / 6.0f));
        wgt[3] = okf * (u3 * (1.0f / 6.0f));
        wgt[1] = okf * ((2.0f / 3.0f) - u2 + 0.5f * u3);
        wgt[2] = okf - wgt[0] - wgt[1] - wgt[3];

        float f[9];
        #pragma unroll
        for (int j = 0; j < 9; ++j) f[j] = 0.0f;
        #pragma unroll
        for (int r = 0; r < 4; ++r) {
            const int j = mi - 3 + r;
            if (j >= 0 && j < 8) f[j] = wgt[r];
        }
        f[8] = __fdividef(x, 1.0f + __expf(-x));   // silu

        #pragma unroll
        for (int j = 0; j < 9; ++j)
            Fs[(i * 9 + j) * MTILE + bl] = f[j];
    }
    __syncthreads();

    // ---- warp split-K GEMM, double-buffered pipeline ----
    const int w    = tid >> 5;       // warp -> k slice (0..3)
    const int lane = tid & 31;
    const int bq   = lane & 3;       // batch row within tile
    const int og   = lane >> 2;      // o-group of 8 (0..7)

    ull acc0 = 0, acc1 = 0, acc2 = 0, acc3 = 0;   // o-pairs og*8 + {01,23,45,67}

    const float* crow = g_C2t + og * 8;
    const int kbeg = w * KSLICE;

    float  a_cur[KG];
    float4 cA_cur[KG], cB_cur[KG];
    float  a_nxt[KG];
    float4 cA_nxt[KG], cB_nxt[KG];

    // prime stage 0
    #pragma unroll
    for (int j = 0; j < KG; ++j) {
        const int k = kbeg + j;
        a_cur[j]  = Fs[k * MTILE + bq];
        cA_cur[j] = __ldg((const float4*)(crow + k * OUT_DIM));
        cB_cur[j] = __ldg((const float4*)(crow + k * OUT_DIM + 4));
    }

    #pragma unroll 2
    for (int g = 1; g < NGRP; ++g) {
        const int kb = kbeg + g * KG;
        // issue next group's loads first (independent of cur)
        #pragma unroll
        for (int j = 0; j < KG; ++j) {
            const int k = kb + j;
            a_nxt[j]  = Fs[k * MTILE + bq];
            cA_nxt[j] = __ldg((const float4*)(crow + k * OUT_DIM));
            cB_nxt[j] = __ldg((const float4*)(crow + k * OUT_DIM + 4));
        }
        // consume current group
        #pragma unroll
        for (int j = 0; j < KG; ++j) {
            const ull a2 = dup2(a_cur[j]);
            union { float4 f; ulonglong2 u; } uA, uB;
            uA.f = cA_cur[j];
            uB.f = cB_cur[j];
            ffma2(acc0, a2, uA.u.x);
            ffma2(acc1, a2, uA.u.y);
            ffma2(acc2, a2, uB.u.x);
            ffma2(acc3, a2, uB.u.y);
        }
        // rotate buffers (register renaming, no copies in SASS)
        #pragma unroll
        for (int j = 0; j < KG; ++j) {
            a_cur[j]  = a_nxt[j];
            cA_cur[j] = cA_nxt[j];
            cB_cur[j] = cB_nxt[j];
        }
    }
    // drain last group
    #pragma unroll
    for (int j = 0; j < KG; ++j) {
        const ull a2 = dup2(a_cur[j]);
        union { float4 f; ulonglong2 u; } uA, uB;
        uA.f = cA_cur[j];
        uB.f = cB_cur[j];
        ffma2(acc0, a2, uA.u.x);
        ffma2(acc1, a2, uA.u.y);
        ffma2(acc2, a2, uB.u.x);
        ffma2(acc3, a2, uB.u.y);
    }

    // partial tile -> smem: Ps[w][bq][o]
    {
        ulonglong2* pdst =
            (ulonglong2*)(Ps + (w * MTILE + bq) * OUT_DIM + og * 8);
        ulonglong2 v0; v0.x = acc0; v0.y = acc1;
        ulonglong2 v1; v1.x = acc2; v1.y = acc3;
        pdst[0] = v0;
        pdst[1] = v1;
    }
    __syncthreads();

    // ---- fixed-order reduce over 4 warp partials, coalesced store ----
    #pragma unroll
    for (int rep = 0; rep < 2; ++rep) {
        const int item = tid + rep * THREADS;   // 0..255 = bl*64 + o
        const int bl = item >> 6;
        const int o  = item & 63;
        float v = 0.0f;
        #pragma unroll
        for (int ww = 0; ww < NWARP; ++ww)
            v += Ps[(ww * MTILE + bl) * OUT_DIM + o];
        const int b = b0 + bl;
        if (b < batch)
            out[b * OUT_DIM + o] = v;
    }
}

extern "C" void kernel_launch(void* const* d_in, const int* in_sizes, int n_in,
                              void* d_out, int out_size)
{
    const float* inp   = (const float*)d_in[0];   // (batch, 64)
    const float* gridp = (const float*)d_in[1];   // (4096, 6)
    const float* coefp = (const float*)d_in[2];   // (4096, 8)
    const float* sbase = (const float*)d_in[3];   // (4096,)
    const float* ssp   = (const float*)d_in[4];   // (4096,)
    const float* maskp = (const float*)d_in[5];   // (4096,)
    float* out = (float*)d_out;                   // (batch, 64)

    const int batch = in_sizes[0] / IN_DIM;

    kan_c2t<<<(KDIM * OUT_DIM + 255) / 256, 256>>>(coefp, sbase, ssp, maskp);

    const int blocks = (batch + MTILE - 1) / MTILE;   // 512 @ batch=2048
    kan_fused<<<blocks, THREADS>>>(inp, gridp, out, batch);
}

// round 13
// speedup vs baseline: 1.4946x; 1.0016x over previous
#include <cuda_runtime.h>

// KAN layer as dense GEMM (R7 structure) with the split-K reduction fused
// into the GEMM epilogue (threadfence + per-mtile counter; the last of the
// 9 k-split blocks reduces in FIXED ks order -> bitwise deterministic).
//
//   kan_feat : Ft[k][b] (k = i*9+j): dense 9-vector per (b,i): 4 nonzero
//              cubic-B-spline weights scattered + silu.
//   kan_c2t  : C2t[k][o] = mask*scale_sp*coef (j<8) | mask*scale_base (j=8)
//   kan_gemm : M=2048,N=64,K=576; split-K x9; 32b x 64o tile, 128 thr,
//              4b x 4o register tile; epilogue: last block per m-tile sums
//              the 9 partials (fixed order) and stores out directly.

#define IN_DIM  64
#define OUT_DIM 64
#define KDIM    (IN_DIM * 9)      // 576
#define MAXB    2048
#define KSPLIT  9
#define KCHUNK  (KDIM / KSPLIT)   // 64
#define MTILE   32
#define MAXMT   (MAXB / MTILE)    // 64

__device__ __align__(16) float g_Ft[KDIM * MAXB];               // 4.5 MB [k][b]
__device__ __align__(16) float g_C2t[KDIM * OUT_DIM];           // 144 KB [k][o]
__device__ __align__(16) float g_Part[KSPLIT * MAXB * OUT_DIM]; // 4.5 MB
__device__ int g_cnt[MAXMT];                                    // zero-init

// ---------------- phase 1: per-(b,i) dense feature vector -------------------
__global__ __launch_bounds__(256)
void kan_feat(const float* __restrict__ inp,
              const float* __restrict__ gridp,
              int batch)
{
    const int tid = blockIdx.x * blockDim.x + threadIdx.x;  // = i*MAXB + b
    const int b = tid & (MAXB - 1);
    const int i = tid >> 11;
    if (i >= IN_DIM) return;

    const float x = (b < batch) ? inp[b * IN_DIM + i] : 0.0f;

    const float g0 = __ldg(gridp + i * 6 + 0);
    const float g5 = __ldg(gridp + i * 6 + 5);
    const float h  = (g5 - g0) * 0.2f;
    const float t0 = g0 - 3.0f * h;
    const float mf = (x - t0) * (1.0f / h);

    int mi = (int)floorf(mf);
    const float ok = (mi >= 0 && mi < 11) ? 1.0f : 0.0f;
    mi = max(0, min(10, mi));

    const float u  = mf - (float)mi;
    const float v  = 1.0f - u;
    const float u2 = u * u;
    const float u3 = u2 * u;
    float w[4];
    w[0] = ok * (v * v * v * (1.0f / 6.0f));
    w[3] = ok * (u3 * (1.0f / 6.0f));
    w[1] = ok * ((2.0f / 3.0f) - u2 + 0.5f * u3);
    w[2] = ok - w[0] - w[1] - w[3];

    float f[9];
    #pragma unroll
    for (int j = 0; j < 9; ++j) f[j] = 0.0f;
    #pragma unroll
    for (int r = 0; r < 4; ++r) {
        const int j = mi - 3 + r;
        if (j >= 0 && j < 8) f[j] = w[r];
    }
    f[8] = __fdividef(x, 1.0f + __expf(-x));   // silu

    #pragma unroll
    for (int j = 0; j < 9; ++j)
        g_Ft[(i * 9 + j) * MAXB + b] = f[j];   // coalesced over b
}

// ---------------- phase 1b: scaled coefficient matrix -----------------------
__global__ __launch_bounds__(256)
void kan_c2t(const float* __restrict__ coefp,
             const float* __restrict__ sbase,
             const float* __restrict__ ssp,
             const float* __restrict__ maskp)
{
    const int tid = blockIdx.x * blockDim.x + threadIdx.x;  // = k*64 + o
    if (tid >= KDIM * OUT_DIM) return;
    const int o = tid & (OUT_DIM - 1);
    const int k = tid >> 6;
    const int i = k / 9;
    const int j = k - i * 9;
    const int s = o * IN_DIM + i;
    const float m = maskp[s];
    g_C2t[tid] = (j < 8) ? m * ssp[s] * __ldg(coefp + s * 8 + j)
                         : m * sbase[s];
}

// ---------------- phase 2: split-K GEMM + fused reduce ----------------------
__global__ __launch_bounds__(128)
void kan_gemm(float* __restrict__ out, int batch)
{
    __shared__ __align__(16) float As[32][36];   // [k][b], pad 4
    __shared__ __align__(16) float Bs[32][64];   // [k][o]
    __shared__ int s_last;

    const int mt = blockIdx.x;        // m-tile
    const int ks = blockIdx.y;        // k-split
    const int b0 = mt * MTILE;
    const int k0 = ks * KCHUNK;

    const int tid = threadIdx.x;
    const int tx = tid & 15;          // o-quad
    const int ty = tid >> 4;          // b-quad (0..7)

    float acc[4][4];
    #pragma unroll
    for (int a = 0; a < 4; ++a)
        #pragma unroll
        for (int c = 0; c < 4; ++c) acc[a][c] = 0.0f;

    #pragma unroll 1
    for (int kk = 0; kk < KCHUNK / 32; ++kk) {
        const int kb = k0 + kk * 32;

        // fill A: 32k x 32b = 256 float4, 2 per thread
        #pragma unroll
        for (int p = 0; p < 2; ++p) {
            const int q  = tid + 128 * p;
            const int ka = q >> 3;
            const int bq = (q & 7) * 4;
            *(float4*)&As[ka][bq] =
                *(const float4*)&g_Ft[(kb + ka) * MAXB + b0 + bq];
        }
        // fill B: 32k x 64o -> 4 float4 per thread
        #pragma unroll
        for (int p = 0; p < 4; ++p) {
            const int q   = tid + 128 * p;
            const int kr  = q >> 4;
            const int oq  = (q & 15) * 4;
            *(float4*)&Bs[kr][oq] =
                *(const float4*)&g_C2t[(kb + kr) * OUT_DIM + oq];
        }
        __syncthreads();

        #pragma unroll
        for (int k = 0; k < 32; ++k) {
            const float4 a = *(const float4*)&As[k][ty * 4];
            const float4 bq = *(const float4*)&Bs[k][tx * 4];
            acc[0][0] = fmaf(a.x, bq.x, acc[0][0]);
            acc[0][1] = fmaf(a.x, bq.y, acc[0][1]);
            acc[0][2] = fmaf(a.x, bq.z, acc[0][2]);
            acc[0][3] = fmaf(a.x, bq.w, acc[0][3]);
            acc[1][0] = fmaf(a.y, bq.x, acc[1][0]);
            acc[1][1] = fmaf(a.y, bq.y, acc[1][1]);
            acc[1][2] = fmaf(a.y, bq.z, acc[1][2]);
            acc[1][3] = fmaf(a.y, bq.w, acc[1][3]);
            acc[2][0] = fmaf(a.z, bq.x, acc[2][0]);
            acc[2][1] = fmaf(a.z, bq.y, acc[2][1]);
            acc[2][2] = fmaf(a.z, bq.z, acc[2][2]);
            acc[2][3] = fmaf(a.z, bq.w, acc[2][3]);
            acc[3][0] = fmaf(a.w, bq.x, acc[3][0]);
            acc[3][1] = fmaf(a.w, bq.y, acc[3][1]);
            acc[3][2] = fmaf(a.w, bq.z, acc[3][2]);
            acc[3][3] = fmaf(a.w, bq.w, acc[3][3]);
        }
        __syncthreads();
    }

    // write partial tile
    #pragma unroll
    for (int ib = 0; ib < 4; ++ib) {
        const int b = b0 + ty * 4 + ib;
        float4 vOut = make_float4(acc[ib][0], acc[ib][1], acc[ib][2], acc[ib][3]);
        *(float4*)&g_Part[((ks << 11) + b) * OUT_DIM + tx * 4] = vOut;
    }

    // ---- fused reduce: last of the KSPLIT blocks for this m-tile sums ----
    __threadfence();                   // my partial visible device-wide
    __syncthreads();                   // all threads' stores issued+fenced
    if (tid == 0) {
        const int old = atomicAdd(&g_cnt[mt], 1);
        s_last = (old == KSPLIT - 1) ? 1 : 0;
    }
    __syncthreads();

    if (s_last) {
        __threadfence();               // acquire other blocks' partials
        // 32b x 64o = 512 float4; 128 threads x 4 passes; fixed ks order.
        const int o4 = (tid & 15) * 4;
        const int br = tid >> 4;       // 0..7
        #pragma unroll
        for (int p = 0; p < 4; ++p) {
            const int bl = br + p * 8;
            const int b  = b0 + bl;
            float4 v = make_float4(0.f, 0.f, 0.f, 0.f);
            #pragma unroll
            for (int kk = 0; kk < KSPLIT; ++kk) {
                const float4 q = *(const float4*)
                    &g_Part[((kk << 11) + b) * OUT_DIM + o4];
                v.x += q.x; v.y += q.y; v.z += q.z; v.w += q.w;
            }
            if (b < batch)
                *(float4*)&out[b * OUT_DIM + o4] = v;
        }
        if (tid == 0) g_cnt[mt] = 0;   // self-reset for next launch/replay
    }
}

extern "C" void kernel_launch(void* const* d_in, const int* in_sizes, int n_in,
                              void* d_out, int out_size)
{
    const float* inp   = (const float*)d_in[0];   // (batch, 64)
    const float* gridp = (const float*)d_in[1];   // (4096, 6)
    const float* coefp = (const float*)d_in[2];   // (4096, 8)
    const float* sbase = (const float*)d_in[3];   // (4096,)
    const float* ssp   = (const float*)d_in[4];   // (4096,)
    const float* maskp = (const float*)d_in[5];   // (4096,)
    float* out = (float*)d_out;                   // (batch, 64)

    int batch = in_sizes[0] / IN_DIM;
    if (batch > MAXB) batch = MAXB;

    kan_feat<<<(IN_DIM * MAXB) / 256, 256>>>(inp, gridp, batch);
    kan_c2t<<<(KDIM * OUT_DIM + 255) / 256, 256>>>(coefp, sbase, ssp, maskp);

    const int mtiles = (batch + MTILE - 1) / MTILE;   // 64 @ batch=2048
    dim3 ggrid(mtiles, KSPLIT);                       // 64 x 9 = 576 blocks
    kan_gemm<<<ggrid, 128>>>(out, batch);
}